// round 9
// baseline (speedup 1.0000x reference)
#include <cuda_runtime.h>

// PartialSum: out[b, p] = sum over 64 contiguous floats of x[b, p*64 : (p+1)*64]
// x: [2048, 65536] f32  -> out: [2048, 1024] f32 (2,097,152 partitions)
//
// Final-form R4 structure (80.4us, 86% DRAM, roofline for this pattern):
// 4 independent, individually warp-coalesced LDG.128 per thread (MLP_p1=4),
// 16 lanes per partition, 4 independent shfl_down trees, writer lane stores.
// This round's single variable: __ldcg (L2-only loads, no L1 install) —
// the last untested cache-path knob. Expected neutral; R4 family stands
// as the converged answer either way.

__global__ void __launch_bounds__(256) partial_sum_kernel(
    const float4* __restrict__ x4, float* __restrict__ out)
{
    int t = threadIdx.x;
    int base = blockIdx.x * 1024 + t;              // float4 index of load 0

    // 4 independent, individually warp-coalesced loads (front-batched, MLP=4)
    float4 a = __ldcg(&x4[base]);
    float4 b = __ldcg(&x4[base + 256]);
    float4 c = __ldcg(&x4[base + 512]);
    float4 d = __ldcg(&x4[base + 768]);

    float sa = (a.x + a.y) + (a.z + a.w);
    float sb = (b.x + b.y) + (b.z + b.w);
    float sc = (c.x + c.y) + (c.z + c.w);
    float sd = (d.x + d.y) + (d.z + d.w);

    // 4 independent 16-lane reduction trees (interleaved for ILP).
    #pragma unroll
    for (int off = 8; off > 0; off >>= 1) {
        sa += __shfl_down_sync(0xffffffffu, sa, off, 16);
        sb += __shfl_down_sync(0xffffffffu, sb, off, 16);
        sc += __shfl_down_sync(0xffffffffu, sc, off, 16);
        sd += __shfl_down_sync(0xffffffffu, sd, off, 16);
    }

    if ((t & 15) == 0) {
        int p = blockIdx.x * 64 + (t >> 4);        // partition of load 0
        out[p]      = sa;
        out[p + 16] = sb;
        out[p + 32] = sc;
        out[p + 48] = sd;
    }
}

extern "C" void kernel_launch(void* const* d_in, const int* in_sizes, int n_in,
                              void* d_out, int out_size)
{
    const float4* x4 = (const float4*)d_in[0];
    float* out = (float*)d_out;

    int blocks = out_size / 64;                    // 2,097,152 / 64 = 32768
    partial_sum_kernel<<<blocks, 256>>>(x4, out);
}

// round 10
// speedup vs baseline: 1.0028x; 1.0028x over previous
#include <cuda_runtime.h>

// PartialSum: out[b, p] = sum over 64 contiguous floats of x[b, p*64 : (p+1)*64]
// x: [2048, 65536] f32  -> out: [2048, 1024] f32 (2,097,152 partitions)
//
// Final probe: sm_103a 256-bit global loads (ld.global.nc.v8.f32).
// Each thread: 2 independent v8 loads, 32B per lane -> each load is a fully
// coalesced contiguous 1KB per warp. 8 lanes per partition, 3-step shfl_down
// reduce, writer lane (t&7)==0 stores. Block covers 4096 floats = 64 parts.

__device__ __forceinline__ float ld256_sum(const float* p)
{
    float a0, a1, a2, a3, a4, a5, a6, a7;
    asm volatile(
        "ld.global.nc.v8.f32 {%0, %1, %2, %3, %4, %5, %6, %7}, [%8];"
        : "=f"(a0), "=f"(a1), "=f"(a2), "=f"(a3),
          "=f"(a4), "=f"(a5), "=f"(a6), "=f"(a7)
        : "l"(p));
    return ((a0 + a1) + (a2 + a3)) + ((a4 + a5) + (a6 + a7));
}

__global__ void __launch_bounds__(256) partial_sum_kernel(
    const float* __restrict__ x, float* __restrict__ out)
{
    int t = threadIdx.x;
    // Block covers 4096 floats. Load A: floats [blk*4096 + t*8, +8)
    // Load B: floats [blk*4096 + 2048 + t*8, +8)
    const float* base = x + (long long)blockIdx.x * 4096 + t * 8;

    // 2 independent 256-bit loads (front-batched).
    float sa = ld256_sum(base);
    float sb = ld256_sum(base + 2048);

    // 8 lanes per partition -> 3-step reduce, two independent trees.
    #pragma unroll
    for (int off = 4; off > 0; off >>= 1) {
        sa += __shfl_down_sync(0xffffffffu, sa, off, 8);
        sb += __shfl_down_sync(0xffffffffu, sb, off, 8);
    }

    if ((t & 7) == 0) {
        int p = blockIdx.x * 64 + (t >> 3);   // partition of load A (0..31)
        out[p]      = sa;
        out[p + 32] = sb;                     // load B: +2048 floats = +32 parts
    }
}

extern "C" void kernel_launch(void* const* d_in, const int* in_sizes, int n_in,
                              void* d_out, int out_size)
{
    const float* x = (const float*)d_in[0];
    float* out = (float*)d_out;

    int blocks = out_size / 64;               // 2,097,152 / 64 = 32768
    partial_sum_kernel<<<blocks, 256>>>(x, out);
}